// round 1
// baseline (speedup 1.0000x reference)
#include <cuda_runtime.h>
#include <cuda_bf16.h>

#define BB 4
#define NBND 262144
#define NATM 8192
#define FF 32

// ---------------- scratch (no allocation allowed) ----------------
__device__ float g_bta[BB * NATM * FF];     // segment sums of bonds_out by bond_atom_1
__device__ float g_cnt[BB * NATM];          // counts
__device__ float g_bond_sum[BB * FF];       // sum over bonds of bonds_out (via sum over atoms of g_bta)
__device__ float g_atom_sum[BB * FF];       // sum over atoms of atoms_out

__device__ __forceinline__ float softplus(float x) {
    // stable: max(x,0) + log1p(exp(-|x|)); __expf is MUFU-based, ~2^-22 rel err
    return fmaxf(x, 0.0f) + log1pf(__expf(-fabsf(x)));
}

// ---------------- zero scratch ----------------
__global__ void zero_kernel() {
    long i = (long)blockIdx.x * 256 + threadIdx.x;
    if (i < (long)BB * NATM * FF) g_bta[i] = 0.0f;
    if (i < BB * NATM) g_cnt[i] = 0.0f;
    if (i < BB * FF) { g_bond_sum[i] = 0.0f; g_atom_sum[i] = 0.0f; }
}

// ---------------- bond kernel: e-MLP (128->64->64->32), 1 thread = 1 bond ----------------
__global__ void __launch_bounds__(128) bond_kernel(
    const float* __restrict__ bonds, const int* __restrict__ ba1,
    const int* __restrict__ ba2, const float* __restrict__ atoms,
    const float* __restrict__ state,
    const float* __restrict__ w1, const float* __restrict__ b1,
    const float* __restrict__ w2, const float* __restrict__ b2,
    const float* __restrict__ w3, const float* __restrict__ b3,
    float* __restrict__ out_bonds)
{
    __shared__ float s_w1[128 * 64];   // 32 KB
    __shared__ float s_w2[64 * 64];    // 16 KB
    __shared__ float s_hst[64];        // bias + state-row contribution (batch-constant)

    const int tid = threadIdx.x;
    for (int i = tid; i < 128 * 64; i += 128) s_w1[i] = w1[i];
    for (int i = tid; i < 64 * 64; i += 128) s_w2[i] = w2[i];
    __syncthreads();

    const long row0 = (long)blockIdx.x * 128;
    const int b = (int)(row0 / NBND);          // block never straddles a batch (NBND%128==0)

    // precompute h1 init = b1 + state @ w1[rows 96..127]
    if (tid < 64) {
        float acc = __ldg(&b1[tid]);
        const float* st = state + b * FF;
        #pragma unroll
        for (int k = 0; k < 32; k++) acc = fmaf(st[k], s_w1[(96 + k) * 64 + tid], acc);
        s_hst[tid] = acc;
    }
    __syncthreads();

    const long row = row0 + tid;               // global bond row
    const int i = (int)(row - (long)b * NBND);
    const int a1 = ba1[b * NBND + i];
    const int a2 = ba2[b * NBND + i];

    float h[64];
    #pragma unroll
    for (int j = 0; j < 64; j++) h[j] = s_hst[j];

    // layer 1: chunks a1, a2, bond (state folded in)
    const float* src0 = atoms + ((long)b * NATM + a1) * FF;
    const float* src1 = atoms + ((long)b * NATM + a2) * FF;
    const float* src2 = bonds + ((long)b * NBND + i) * FF;
    #pragma unroll
    for (int c = 0; c < 3; c++) {
        const float* src = (c == 0) ? src0 : (c == 1) ? src1 : src2;
        float4 xv[8];
        const float4* p = (const float4*)src;
        #pragma unroll
        for (int q = 0; q < 8; q++) xv[q] = __ldg(&p[q]);
        const float* xf = (const float*)xv;
        #pragma unroll
        for (int k = 0; k < 32; k++) {
            const float xk = xf[k];
            const float* wr = &s_w1[(c * 32 + k) * 64];
            #pragma unroll
            for (int j = 0; j < 64; j++) h[j] = fmaf(xk, wr[j], h[j]);
        }
    }

    // layer 2
    float h2[64];
    #pragma unroll
    for (int j = 0; j < 64; j++) h2[j] = __ldg(&b2[j]);
    #pragma unroll
    for (int k = 0; k < 64; k++) {
        const float xk = softplus(h[k]);
        const float* wr = &s_w2[k * 64];
        #pragma unroll
        for (int j = 0; j < 64; j++) h2[j] = fmaf(xk, wr[j], h2[j]);
    }

    // layer 3 (weights via __ldg: broadcast, L1-resident)
    float o[32];
    #pragma unroll
    for (int j = 0; j < 32; j++) o[j] = __ldg(&b3[j]);
    #pragma unroll
    for (int k = 0; k < 64; k++) {
        const float xk = softplus(h2[k]);
        #pragma unroll
        for (int j = 0; j < 32; j++) o[j] = fmaf(xk, __ldg(&w3[k * 32 + j]), o[j]);
    }
    #pragma unroll
    for (int j = 0; j < 32; j++) o[j] = softplus(o[j]);

    // write bonds_out (contiguous 128B row per thread)
    float* orow = out_bonds + row * FF;
    #pragma unroll
    for (int q = 0; q < 8; q++)
        ((float4*)orow)[q] = make_float4(o[q * 4], o[q * 4 + 1], o[q * 4 + 2], o[q * 4 + 3]);

    // scatter-add to per-atom sums + count
    float* dst = &g_bta[((long)b * NATM + a1) * FF];
    #pragma unroll
    for (int j = 0; j < 32; j++) atomicAdd(&dst[j], o[j]);
    atomicAdd(&g_cnt[b * NATM + a1], 1.0f);
}

// warp butterfly: reduce each of 32 per-thread values across the warp; lane j keeps feature j
__device__ __forceinline__ float warp_reduce_rows(const float* v, int lane) {
    float part = 0.0f;
    #pragma unroll
    for (int j = 0; j < 32; j++) {
        float x = v[j];
        x += __shfl_xor_sync(0xffffffffu, x, 16);
        x += __shfl_xor_sync(0xffffffffu, x, 8);
        x += __shfl_xor_sync(0xffffffffu, x, 4);
        x += __shfl_xor_sync(0xffffffffu, x, 2);
        x += __shfl_xor_sync(0xffffffffu, x, 1);
        if (lane == j) part = x;
    }
    return part;
}

// ---------------- atom kernel: v-MLP (96->64->64->32), 1 thread = 1 atom ----------------
__global__ void __launch_bounds__(128) atom_kernel(
    const float* __restrict__ atoms, const float* __restrict__ state,
    const float* __restrict__ w1, const float* __restrict__ b1,
    const float* __restrict__ w2, const float* __restrict__ b2,
    const float* __restrict__ w3, const float* __restrict__ b3,
    float* __restrict__ out_atoms)
{
    __shared__ float s_w1[96 * 64];    // 24 KB
    __shared__ float s_w2[64 * 64];    // 16 KB
    __shared__ float s_hst[64];
    __shared__ float s_red[2][4][32];  // [which][warp][feature]

    const int tid = threadIdx.x;
    const int lane = tid & 31;
    const int warp = tid >> 5;
    for (int i = tid; i < 96 * 64; i += 128) s_w1[i] = w1[i];
    for (int i = tid; i < 64 * 64; i += 128) s_w2[i] = w2[i];
    __syncthreads();

    const long row0 = (long)blockIdx.x * 128;
    const int b = (int)(row0 / NATM);

    if (tid < 64) {
        float acc = __ldg(&b1[tid]);
        const float* st = state + b * FF;
        #pragma unroll
        for (int k = 0; k < 32; k++) acc = fmaf(st[k], s_w1[(64 + k) * 64 + tid], acc);
        s_hst[tid] = acc;
    }
    __syncthreads();

    const long row = row0 + tid;
    const int a = (int)(row - (long)b * NATM);

    // chunk 0: raw per-atom bond sums (reduced across block -> global bond mean), then scaled
    float x0[32];
    const float* braw = &g_bta[((long)b * NATM + a) * FF];
    #pragma unroll
    for (int k = 0; k < 32; k++) x0[k] = braw[k];
    s_red[0][warp][lane] = warp_reduce_rows(x0, lane);

    const float invc = 1.0f / g_cnt[b * NATM + a];

    float h[64];
    #pragma unroll
    for (int j = 0; j < 64; j++) h[j] = s_hst[j];

    #pragma unroll
    for (int k = 0; k < 32; k++) {
        const float xk = x0[k] * invc;
        const float* wr = &s_w1[k * 64];
        #pragma unroll
        for (int j = 0; j < 64; j++) h[j] = fmaf(xk, wr[j], h[j]);
    }
    const float* arow = atoms + ((long)b * NATM + a) * FF;
    #pragma unroll
    for (int k = 0; k < 32; k++) {
        const float xk = __ldg(&arow[k]);
        const float* wr = &s_w1[(32 + k) * 64];
        #pragma unroll
        for (int j = 0; j < 64; j++) h[j] = fmaf(xk, wr[j], h[j]);
    }

    float h2[64];
    #pragma unroll
    for (int j = 0; j < 64; j++) h2[j] = __ldg(&b2[j]);
    #pragma unroll
    for (int k = 0; k < 64; k++) {
        const float xk = softplus(h[k]);
        const float* wr = &s_w2[k * 64];
        #pragma unroll
        for (int j = 0; j < 64; j++) h2[j] = fmaf(xk, wr[j], h2[j]);
    }

    float o[32];
    #pragma unroll
    for (int j = 0; j < 32; j++) o[j] = __ldg(&b3[j]);
    #pragma unroll
    for (int k = 0; k < 64; k++) {
        const float xk = softplus(h2[k]);
        #pragma unroll
        for (int j = 0; j < 32; j++) o[j] = fmaf(xk, __ldg(&w3[k * 32 + j]), o[j]);
    }
    #pragma unroll
    for (int j = 0; j < 32; j++) o[j] = softplus(o[j]);

    float* orow = out_atoms + row * FF;
    #pragma unroll
    for (int q = 0; q < 8; q++)
        ((float4*)orow)[q] = make_float4(o[q * 4], o[q * 4 + 1], o[q * 4 + 2], o[q * 4 + 3]);

    // block-reduce atoms_out for atom mean
    s_red[1][warp][lane] = warp_reduce_rows(o, lane);
    __syncthreads();
    if (warp == 0) {
        float bs = s_red[0][0][lane] + s_red[0][1][lane] + s_red[0][2][lane] + s_red[0][3][lane];
        float as = s_red[1][0][lane] + s_red[1][1][lane] + s_red[1][2][lane] + s_red[1][3][lane];
        atomicAdd(&g_bond_sum[b * FF + lane], bs);
        atomicAdd(&g_atom_sum[b * FF + lane], as);
    }
}

// ---------------- state kernel: u-MLP (96->64->64->32), 1 block = 1 batch ----------------
__global__ void __launch_bounds__(64) state_kernel(
    const float* __restrict__ state,
    const float* __restrict__ w1, const float* __restrict__ b1,
    const float* __restrict__ w2, const float* __restrict__ b2,
    const float* __restrict__ w3, const float* __restrict__ b3,
    float* __restrict__ out_state)
{
    __shared__ float u_in[96];
    __shared__ float h1s[64];
    __shared__ float h2s[64];
    const int b = blockIdx.x;
    const int t = threadIdx.x;
    if (t < 32) {
        u_in[t]      = g_bond_sum[b * FF + t] * (1.0f / NBND);
        u_in[32 + t] = g_atom_sum[b * FF + t] * (1.0f / NATM);
        u_in[64 + t] = state[b * FF + t];
    }
    __syncthreads();
    {
        float acc = __ldg(&b1[t]);
        for (int k = 0; k < 96; k++) acc = fmaf(u_in[k], __ldg(&w1[k * 64 + t]), acc);
        h1s[t] = softplus(acc);
    }
    __syncthreads();
    {
        float acc = __ldg(&b2[t]);
        for (int k = 0; k < 64; k++) acc = fmaf(h1s[k], __ldg(&w2[k * 64 + t]), acc);
        h2s[t] = softplus(acc);
    }
    __syncthreads();
    if (t < 32) {
        float acc = __ldg(&b3[t]);
        for (int k = 0; k < 64; k++) acc = fmaf(h2s[k], __ldg(&w3[k * 32 + t]), acc);
        out_state[b * FF + t] = softplus(acc);
    }
}

extern "C" void kernel_launch(void* const* d_in, const int* in_sizes, int n_in,
                              void* d_out, int out_size)
{
    const float* bonds = (const float*)d_in[0];
    const int*   ba1   = (const int*)d_in[1];
    const int*   ba2   = (const int*)d_in[2];
    const float* atoms = (const float*)d_in[3];
    const float* state = (const float*)d_in[4];
    const float* ew1 = (const float*)d_in[5];
    const float* eb1 = (const float*)d_in[6];
    const float* ew2 = (const float*)d_in[7];
    const float* eb2 = (const float*)d_in[8];
    const float* ew3 = (const float*)d_in[9];
    const float* eb3 = (const float*)d_in[10];
    const float* vw1 = (const float*)d_in[11];
    const float* vb1 = (const float*)d_in[12];
    const float* vw2 = (const float*)d_in[13];
    const float* vb2 = (const float*)d_in[14];
    const float* vw3 = (const float*)d_in[15];
    const float* vb3 = (const float*)d_in[16];
    const float* uw1 = (const float*)d_in[17];
    const float* ub1 = (const float*)d_in[18];
    const float* uw2 = (const float*)d_in[19];
    const float* ub2 = (const float*)d_in[20];
    const float* uw3 = (const float*)d_in[21];
    const float* ub3 = (const float*)d_in[22];

    float* out = (float*)d_out;
    float* out_bonds = out;                                    // B*NB*32
    float* out_atoms = out + (long)BB * NBND * FF;             // B*NA*32
    float* out_state = out_atoms + (long)BB * NATM * FF;       // B*32

    zero_kernel<<<(BB * NATM * FF + 255) / 256, 256>>>();
    bond_kernel<<<(BB * NBND) / 128, 128>>>(bonds, ba1, ba2, atoms, state,
                                            ew1, eb1, ew2, eb2, ew3, eb3, out_bonds);
    atom_kernel<<<(BB * NATM) / 128, 128>>>(atoms, state,
                                            vw1, vb1, vw2, vb2, vw3, vb3, out_atoms);
    state_kernel<<<BB, 64>>>(state, uw1, ub1, uw2, ub2, uw3, ub3, out_state);
}

// round 2
// speedup vs baseline: 1.7223x; 1.7223x over previous
#include <cuda_runtime.h>
#include <cuda_bf16.h>

#define BB 4
#define NBND 262144
#define NATM 8192
#define FF 32

typedef unsigned long long u64;

// ---------------- scratch (no allocation allowed) ----------------
__device__ float g_bta[BB * NATM * FF];     // segment sums of bonds_out by bond_atom_1
__device__ float g_cnt[BB * NATM];          // counts
__device__ float g_bond_sum[BB * FF];       // sum over bonds of bonds_out
__device__ float g_atom_sum[BB * FF];       // sum over atoms of atoms_out

__device__ __forceinline__ float softplus(float x) {
    // stable: max(x,0) + log(1 + exp(-|x|)); arg of log in (1,2] -> __logf safe
    return fmaxf(x, 0.0f) + __logf(1.0f + __expf(-fabsf(x)));
}

__device__ __forceinline__ u64 pack2(float lo, float hi) {
    u64 r; asm("mov.b64 %0, {%1, %2};" : "=l"(r) : "f"(lo), "f"(hi)); return r;
}
__device__ __forceinline__ u64 pack2s(float x) { return pack2(x, x); }
__device__ __forceinline__ void unpack2(u64 v, float& lo, float& hi) {
    asm("mov.b64 {%0, %1}, %2;" : "=f"(lo), "=f"(hi) : "l"(v));
}
__device__ __forceinline__ void fma2(u64& d, u64 a, u64 b) {
    asm("fma.rn.f32x2 %0, %1, %2, %0;" : "+l"(d) : "l"(a), "l"(b));
}

// ---------------- zero scratch ----------------
__global__ void zero_kernel() {
    long i = (long)blockIdx.x * 256 + threadIdx.x;
    if (i < (long)BB * NATM * FF) g_bta[i] = 0.0f;
    if (i < BB * NATM) g_cnt[i] = 0.0f;
    if (i < BB * FF) { g_bond_sum[i] = 0.0f; g_atom_sum[i] = 0.0f; }
}

// ---------------- bond kernel: e-MLP (128->64->64->32), 1 thread = 1 bond ----------------
__global__ void __launch_bounds__(256, 1) bond_kernel(
    const float* __restrict__ bonds, const int* __restrict__ ba1,
    const int* __restrict__ ba2, const float* __restrict__ atoms,
    const float* __restrict__ state,
    const float* __restrict__ w1, const float* __restrict__ b1,
    const float* __restrict__ w2, const float* __restrict__ b2,
    const float* __restrict__ w3, const float* __restrict__ b3,
    float* __restrict__ out_bonds)
{
    __shared__ __align__(16) float s_w1[128 * 64];   // 32 KB; reused for w3 after layer 1
    __shared__ __align__(16) float s_w2[64 * 64];    // 16 KB
    __shared__ __align__(16) float s_hst[64];        // b1 + state-row contribution

    const int tid = threadIdx.x;
    for (int i = tid; i < 128 * 64; i += 256) s_w1[i] = w1[i];
    for (int i = tid; i < 64 * 64; i += 256) s_w2[i] = w2[i];
    __syncthreads();

    const long row0 = (long)blockIdx.x * 256;
    const int b = (int)(row0 / NBND);          // 256 | NBND, block never straddles batch

    if (tid < 64) {
        float acc = __ldg(&b1[tid]);
        const float* st = state + b * FF;
        #pragma unroll
        for (int k = 0; k < 32; k++) acc = fmaf(st[k], s_w1[(96 + k) * 64 + tid], acc);
        s_hst[tid] = acc;
    }
    __syncthreads();

    const long row = row0 + tid;
    const int i = (int)(row - (long)b * NBND);
    const int a1 = ba1[b * NBND + i];
    const int a2 = ba2[b * NBND + i];

    // packed accumulators: h[j] holds outputs (2j, 2j+1)
    u64 h[32];
    {
        const u64* hs = (const u64*)s_hst;
        #pragma unroll
        for (int j = 0; j < 32; j++) h[j] = hs[j];
    }

    // ---- layer 1: chunks a1, a2, bond (state folded into s_hst) ----
    const float* src0 = atoms + ((long)b * NATM + a1) * FF;
    const float* src1 = atoms + ((long)b * NATM + a2) * FF;
    const float* src2 = bonds + ((long)b * NBND + i) * FF;
    #pragma unroll
    for (int c = 0; c < 3; c++) {
        const float* src = (c == 0) ? src0 : (c == 1) ? src1 : src2;
        float4 xv[8];
        const float4* p = (const float4*)src;
        #pragma unroll
        for (int q = 0; q < 8; q++) xv[q] = __ldg(&p[q]);
        const float* xf = (const float*)xv;
        #pragma unroll
        for (int k = 0; k < 32; k++) {
            const u64 xk2 = pack2s(xf[k]);
            const ulonglong2* wr = (const ulonglong2*)&s_w1[(c * 32 + k) * 64];
            #pragma unroll
            for (int j = 0; j < 16; j++) {
                ulonglong2 w = wr[j];
                fma2(h[2 * j], xk2, w.x);
                fma2(h[2 * j + 1], xk2, w.y);
            }
        }
    }

    // all reads of s_w1 done -> stage w3 into its space, overlapped with layer 2
    __syncthreads();
    for (int t = tid; t < 64 * 32; t += 256) s_w1[t] = w3[t];

    // ---- layer 2 ----
    u64 h2[32];
    {
        const u64* bp = (const u64*)b2;
        #pragma unroll
        for (int j = 0; j < 32; j++) h2[j] = __ldg(&bp[j]);
    }
    #pragma unroll
    for (int kp = 0; kp < 32; kp++) {
        float xa, xb;
        unpack2(h[kp], xa, xb);
        const u64 xa2 = pack2s(softplus(xa));
        const u64 xb2 = pack2s(softplus(xb));
        const ulonglong2* wa = (const ulonglong2*)&s_w2[(2 * kp) * 64];
        const ulonglong2* wb = (const ulonglong2*)&s_w2[(2 * kp + 1) * 64];
        #pragma unroll
        for (int j = 0; j < 16; j++) {
            ulonglong2 w = wa[j];
            fma2(h2[2 * j], xa2, w.x);
            fma2(h2[2 * j + 1], xa2, w.y);
        }
        #pragma unroll
        for (int j = 0; j < 16; j++) {
            ulonglong2 w = wb[j];
            fma2(h2[2 * j], xb2, w.x);
            fma2(h2[2 * j + 1], xb2, w.y);
        }
    }

    __syncthreads();   // w3 staged

    // ---- layer 3 (w3 now in s_w1) ----
    u64 o[16];
    {
        const u64* bp = (const u64*)b3;
        #pragma unroll
        for (int j = 0; j < 16; j++) o[j] = __ldg(&bp[j]);
    }
    #pragma unroll
    for (int kp = 0; kp < 32; kp++) {
        float xa, xb;
        unpack2(h2[kp], xa, xb);
        const u64 xa2 = pack2s(softplus(xa));
        const u64 xb2 = pack2s(softplus(xb));
        const ulonglong2* wa = (const ulonglong2*)&s_w1[(2 * kp) * 32];
        const ulonglong2* wb = (const ulonglong2*)&s_w1[(2 * kp + 1) * 32];
        #pragma unroll
        for (int j = 0; j < 8; j++) {
            ulonglong2 w = wa[j];
            fma2(o[2 * j], xa2, w.x);
            fma2(o[2 * j + 1], xa2, w.y);
        }
        #pragma unroll
        for (int j = 0; j < 8; j++) {
            ulonglong2 w = wb[j];
            fma2(o[2 * j], xb2, w.x);
            fma2(o[2 * j + 1], xb2, w.y);
        }
    }

    float of[32];
    #pragma unroll
    for (int j = 0; j < 16; j++) {
        float a, bq;
        unpack2(o[j], a, bq);
        of[2 * j] = softplus(a);
        of[2 * j + 1] = softplus(bq);
    }

    float* orow = out_bonds + row * FF;
    #pragma unroll
    for (int q = 0; q < 8; q++)
        ((float4*)orow)[q] = make_float4(of[q * 4], of[q * 4 + 1], of[q * 4 + 2], of[q * 4 + 3]);

    float* dst = &g_bta[((long)b * NATM + a1) * FF];
    #pragma unroll
    for (int j = 0; j < 32; j++) atomicAdd(&dst[j], of[j]);
    atomicAdd(&g_cnt[b * NATM + a1], 1.0f);
}

// warp butterfly: reduce each of 32 per-thread values across the warp; lane j keeps feature j
__device__ __forceinline__ float warp_reduce_rows(const float* v, int lane) {
    float part = 0.0f;
    #pragma unroll
    for (int j = 0; j < 32; j++) {
        float x = v[j];
        x += __shfl_xor_sync(0xffffffffu, x, 16);
        x += __shfl_xor_sync(0xffffffffu, x, 8);
        x += __shfl_xor_sync(0xffffffffu, x, 4);
        x += __shfl_xor_sync(0xffffffffu, x, 2);
        x += __shfl_xor_sync(0xffffffffu, x, 1);
        if (lane == j) part = x;
    }
    return part;
}

// ---------------- atom kernel: v-MLP (96->64->64->32), 1 thread = 1 atom ----------------
__global__ void __launch_bounds__(128, 1) atom_kernel(
    const float* __restrict__ atoms, const float* __restrict__ state,
    const float* __restrict__ w1, const float* __restrict__ b1,
    const float* __restrict__ w2, const float* __restrict__ b2,
    const float* __restrict__ w3, const float* __restrict__ b3,
    float* __restrict__ out_atoms)
{
    __shared__ __align__(16) float s_w1[96 * 64];    // 24 KB; reused for w3
    __shared__ __align__(16) float s_w2[64 * 64];    // 16 KB
    __shared__ __align__(16) float s_hst[64];
    __shared__ float s_red[2][4][32];

    const int tid = threadIdx.x;
    const int lane = tid & 31;
    const int warp = tid >> 5;
    for (int i = tid; i < 96 * 64; i += 128) s_w1[i] = w1[i];
    for (int i = tid; i < 64 * 64; i += 128) s_w2[i] = w2[i];
    __syncthreads();

    const long row0 = (long)blockIdx.x * 128;
    const int b = (int)(row0 / NATM);

    if (tid < 64) {
        float acc = __ldg(&b1[tid]);
        const float* st = state + b * FF;
        #pragma unroll
        for (int k = 0; k < 32; k++) acc = fmaf(st[k], s_w1[(64 + k) * 64 + tid], acc);
        s_hst[tid] = acc;
    }
    __syncthreads();

    const long row = row0 + tid;
    const int a = (int)(row - (long)b * NATM);

    // chunk 0 input: raw per-atom bond sums (also reduced for global bond mean)
    float x0[32];
    const float* braw = &g_bta[((long)b * NATM + a) * FF];
    #pragma unroll
    for (int k = 0; k < 32; k++) x0[k] = braw[k];
    s_red[0][warp][lane] = warp_reduce_rows(x0, lane);

    const float invc = 1.0f / g_cnt[b * NATM + a];

    u64 h[32];
    {
        const u64* hs = (const u64*)s_hst;
        #pragma unroll
        for (int j = 0; j < 32; j++) h[j] = hs[j];
    }

    #pragma unroll
    for (int k = 0; k < 32; k++) {
        const u64 xk2 = pack2s(x0[k] * invc);
        const ulonglong2* wr = (const ulonglong2*)&s_w1[k * 64];
        #pragma unroll
        for (int j = 0; j < 16; j++) {
            ulonglong2 w = wr[j];
            fma2(h[2 * j], xk2, w.x);
            fma2(h[2 * j + 1], xk2, w.y);
        }
    }
    {
        const float4* p = (const float4*)(atoms + ((long)b * NATM + a) * FF);
        float4 xv[8];
        #pragma unroll
        for (int q = 0; q < 8; q++) xv[q] = __ldg(&p[q]);
        const float* xf = (const float*)xv;
        #pragma unroll
        for (int k = 0; k < 32; k++) {
            const u64 xk2 = pack2s(xf[k]);
            const ulonglong2* wr = (const ulonglong2*)&s_w1[(32 + k) * 64];
            #pragma unroll
            for (int j = 0; j < 16; j++) {
                ulonglong2 w = wr[j];
                fma2(h[2 * j], xk2, w.x);
                fma2(h[2 * j + 1], xk2, w.y);
            }
        }
    }

    __syncthreads();
    for (int t = tid; t < 64 * 32; t += 128) s_w1[t] = w3[t];

    u64 h2[32];
    {
        const u64* bp = (const u64*)b2;
        #pragma unroll
        for (int j = 0; j < 32; j++) h2[j] = __ldg(&bp[j]);
    }
    #pragma unroll
    for (int kp = 0; kp < 32; kp++) {
        float xa, xb;
        unpack2(h[kp], xa, xb);
        const u64 xa2 = pack2s(softplus(xa));
        const u64 xb2 = pack2s(softplus(xb));
        const ulonglong2* wa = (const ulonglong2*)&s_w2[(2 * kp) * 64];
        const ulonglong2* wb = (const ulonglong2*)&s_w2[(2 * kp + 1) * 64];
        #pragma unroll
        for (int j = 0; j < 16; j++) {
            ulonglong2 w = wa[j];
            fma2(h2[2 * j], xa2, w.x);
            fma2(h2[2 * j + 1], xa2, w.y);
        }
        #pragma unroll
        for (int j = 0; j < 16; j++) {
            ulonglong2 w = wb[j];
            fma2(h2[2 * j], xb2, w.x);
            fma2(h2[2 * j + 1], xb2, w.y);
        }
    }

    __syncthreads();   // w3 staged

    u64 o[16];
    {
        const u64* bp = (const u64*)b3;
        #pragma unroll
        for (int j = 0; j < 16; j++) o[j] = __ldg(&bp[j]);
    }
    #pragma unroll
    for (int kp = 0; kp < 32; kp++) {
        float xa, xb;
        unpack2(h2[kp], xa, xb);
        const u64 xa2 = pack2s(softplus(xa));
        const u64 xb2 = pack2s(softplus(xb));
        const ulonglong2* wa = (const ulonglong2*)&s_w1[(2 * kp) * 32];
        const ulonglong2* wb = (const ulonglong2*)&s_w1[(2 * kp + 1) * 32];
        #pragma unroll
        for (int j = 0; j < 8; j++) {
            ulonglong2 w = wa[j];
            fma2(o[2 * j], xa2, w.x);
            fma2(o[2 * j + 1], xa2, w.y);
        }
        #pragma unroll
        for (int j = 0; j < 8; j++) {
            ulonglong2 w = wb[j];
            fma2(o[2 * j], xb2, w.x);
            fma2(o[2 * j + 1], xb2, w.y);
        }
    }

    float of[32];
    #pragma unroll
    for (int j = 0; j < 16; j++) {
        float xa, xb;
        unpack2(o[j], xa, xb);
        of[2 * j] = softplus(xa);
        of[2 * j + 1] = softplus(xb);
    }

    float* orow = out_atoms + row * FF;
    #pragma unroll
    for (int q = 0; q < 8; q++)
        ((float4*)orow)[q] = make_float4(of[q * 4], of[q * 4 + 1], of[q * 4 + 2], of[q * 4 + 3]);

    s_red[1][warp][lane] = warp_reduce_rows(of, lane);
    __syncthreads();
    if (warp == 0) {
        float bs = s_red[0][0][lane] + s_red[0][1][lane] + s_red[0][2][lane] + s_red[0][3][lane];
        float as = s_red[1][0][lane] + s_red[1][1][lane] + s_red[1][2][lane] + s_red[1][3][lane];
        atomicAdd(&g_bond_sum[b * FF + lane], bs);
        atomicAdd(&g_atom_sum[b * FF + lane], as);
    }
}

// ---------------- state kernel: u-MLP (96->64->64->32), 1 block = 1 batch ----------------
__global__ void __launch_bounds__(64) state_kernel(
    const float* __restrict__ state,
    const float* __restrict__ w1, const float* __restrict__ b1,
    const float* __restrict__ w2, const float* __restrict__ b2,
    const float* __restrict__ w3, const float* __restrict__ b3,
    float* __restrict__ out_state)
{
    __shared__ float u_in[96];
    __shared__ float h1s[64];
    __shared__ float h2s[64];
    const int b = blockIdx.x;
    const int t = threadIdx.x;
    if (t < 32) {
        u_in[t]      = g_bond_sum[b * FF + t] * (1.0f / NBND);
        u_in[32 + t] = g_atom_sum[b * FF + t] * (1.0f / NATM);
        u_in[64 + t] = state[b * FF + t];
    }
    __syncthreads();
    {
        float acc = __ldg(&b1[t]);
        for (int k = 0; k < 96; k++) acc = fmaf(u_in[k], __ldg(&w1[k * 64 + t]), acc);
        h1s[t] = softplus(acc);
    }
    __syncthreads();
    {
        float acc = __ldg(&b2[t]);
        for (int k = 0; k < 64; k++) acc = fmaf(h1s[k], __ldg(&w2[k * 64 + t]), acc);
        h2s[t] = softplus(acc);
    }
    __syncthreads();
    if (t < 32) {
        float acc = __ldg(&b3[t]);
        for (int k = 0; k < 64; k++) acc = fmaf(h2s[k], __ldg(&w3[k * 32 + t]), acc);
        out_state[b * FF + t] = softplus(acc);
    }
}

extern "C" void kernel_launch(void* const* d_in, const int* in_sizes, int n_in,
                              void* d_out, int out_size)
{
    const float* bonds = (const float*)d_in[0];
    const int*   ba1   = (const int*)d_in[1];
    const int*   ba2   = (const int*)d_in[2];
    const float* atoms = (const float*)d_in[3];
    const float* state = (const float*)d_in[4];
    const float* ew1 = (const float*)d_in[5];
    const float* eb1 = (const float*)d_in[6];
    const float* ew2 = (const float*)d_in[7];
    const float* eb2 = (const float*)d_in[8];
    const float* ew3 = (const float*)d_in[9];
    const float* eb3 = (const float*)d_in[10];
    const float* vw1 = (const float*)d_in[11];
    const float* vb1 = (const float*)d_in[12];
    const float* vw2 = (const float*)d_in[13];
    const float* vb2 = (const float*)d_in[14];
    const float* vw3 = (const float*)d_in[15];
    const float* vb3 = (const float*)d_in[16];
    const float* uw1 = (const float*)d_in[17];
    const float* ub1 = (const float*)d_in[18];
    const float* uw2 = (const float*)d_in[19];
    const float* ub2 = (const float*)d_in[20];
    const float* uw3 = (const float*)d_in[21];
    const float* ub3 = (const float*)d_in[22];

    float* out = (float*)d_out;
    float* out_bonds = out;                                    // B*NB*32
    float* out_atoms = out + (long)BB * NBND * FF;             // B*NA*32
    float* out_state = out_atoms + (long)BB * NATM * FF;       // B*32

    zero_kernel<<<(BB * NATM * FF + 255) / 256, 256>>>();
    bond_kernel<<<(BB * NBND) / 256, 256>>>(bonds, ba1, ba2, atoms, state,
                                            ew1, eb1, ew2, eb2, ew3, eb3, out_bonds);
    atom_kernel<<<(BB * NATM) / 128, 128>>>(atoms, state,
                                            vw1, vb1, vw2, vb2, vw3, vb3, out_atoms);
    state_kernel<<<BB, 64>>>(state, uw1, ub1, uw2, ub2, uw3, ub3, out_state);
}